// round 7
// baseline (speedup 1.0000x reference)
#include <cuda_runtime.h>
#include <cuda_fp16.h>
#include <math.h>
#include <stdint.h>

#define H_DIM   1024
#define LS_DIM  2048
#define BATCH   4
#define SEQ     2048
#define NTOK    8192
#define PROJ_W  384
#define CHUNK   64
#define NCHUNK  32
#define CAT_NKT 66            // 64 ktiles of t (k=2048) + 2 ktiles of sr (k=64)

// -------- scratch (device globals; allocation-free rule) --------------------
__device__ __half g_xh[(size_t)NTOK * H_DIM];               // A tiles [mt64][kt32][4096h]
__device__ float  g_proj[(size_t)NTOK * PROJ_W];
__device__ float  g_decay[NTOK];
__device__ __half g_cat[(size_t)64 * CAT_NKT * 4096];       // [t|sr] A tiles
__device__ __half g_wp[(size_t)2 * 32 * 8192];              // B tiles (N padded to 512)
__device__ __half g_wug[(size_t)16 * 32 * 8192];            // B tiles [u64|g64]x32, N=4096
__device__ __half g_wcat[(size_t)4 * CAT_NKT * 8192];       // B tiles [Wdown;Wrec], N=1024
__device__ float  g_cA[BATCH * NCHUNK];
__device__ float  g_cB[(size_t)BATCH * NCHUNK * 4096];
__device__ float  g_cS[(size_t)BATCH * NCHUNK * 4096];

// ---------------------------------------------------------------------------
__device__ __forceinline__ float silu_f(float x) { return x / (1.0f + expf(-x)); }

__device__ __forceinline__ void mma_h(float* c, uint4 a, uint32_t b0, uint32_t b1) {
    asm volatile(
        "mma.sync.aligned.m16n8k16.row.col.f32.f16.f16.f32 "
        "{%0,%1,%2,%3}, {%4,%5,%6,%7}, {%8,%9}, {%0,%1,%2,%3};"
        : "+f"(c[0]), "+f"(c[1]), "+f"(c[2]), "+f"(c[3])
        : "r"(a.x), "r"(a.y), "r"(a.z), "r"(a.w), "r"(b0), "r"(b1));
}

#define CP16(s, g)  asm volatile("cp.async.cg.shared.global [%0], [%1], 16;" :: "r"(s), "l"(g))
#define CPCOMMITG() asm volatile("cp.async.commit_group;" ::: "memory")
#define CPWAIT2()   asm volatile("cp.async.wait_group 2;" ::: "memory")

// A-tile half offset within a 128(m) x 32(k) tile (4096 halfs)
__device__ __forceinline__ int ah_off(int m, int k) {
    int wr = m >> 6, mi = (m >> 4) & 3, h = (m >> 3) & 1, g = m & 7;
    int ks = k >> 4, u = (k >> 3) & 1, tg = (k >> 1) & 3, e = k & 1;
    return ((((wr * 2 + ks) * 4 + mi) * 32 + g * 4 + tg) * 4 + h + 2 * u) * 2 + e;
}

// ---------------------------------------------------------------------------
// fp16 GEMM body. 256 threads = 8 warps (2x4), warp tile 64x64. BM=128,BN=256,
// ktile=32. 4-stage cp.async (96KB dynamic smem). A tile 8KB, B tile 16KB.
// WB 0: natural fp32 store (guard col<Nlim). WB 1: fused swiglu -> g_cat tiles.
// ---------------------------------------------------------------------------
template <int WB>
__device__ __forceinline__ void gemm_body(
    const __half* __restrict__ A, const __half* __restrict__ B, void* __restrict__ Cv,
    int nkt, int ldc, int Nlim, int bx, int by, uint32_t* smw)
{
    const int tid = threadIdx.x;
    const int w = tid >> 5, lane = tid & 31;
    const int wr = w & 1, wc = w >> 1;        // 2 x 4 warp grid
    const int g = lane >> 2, tg = lane & 3;

    const __half* Ab = A + (size_t)by * nkt * 4096;
    const __half* Bb = B + (size_t)bx * nkt * 8192;
    const uint32_t sbase = (uint32_t)__cvta_generic_to_shared(smw);

    float acc[4][8][4];
#pragma unroll
    for (int mi = 0; mi < 4; ++mi)
#pragma unroll
        for (int j = 0; j < 8; ++j)
#pragma unroll
            for (int q = 0; q < 4; ++q) acc[mi][j][q] = 0.0f;

#pragma unroll
    for (int p = 0; p < 3; ++p) {
        uint32_t sa = sbase + p * 24576u + tid * 32u;
        const __half* ga = Ab + (size_t)p * 4096 + tid * 16;
        CP16(sa, ga); CP16(sa + 16, ga + 8);
        uint32_t sbB = sbase + p * 24576u + 8192u + tid * 64u;
        const __half* gb = Bb + (size_t)p * 8192 + tid * 32;
        CP16(sbB, gb); CP16(sbB + 16, gb + 8); CP16(sbB + 32, gb + 16); CP16(sbB + 48, gb + 24);
        CPCOMMITG();
    }

    for (int t = 0; t < nkt; ++t) {
        const int s = t & 3;
        CPWAIT2();
        __syncthreads();
        if (t + 3 < nkt) {
            const int p = (t + 3) & 3;
            uint32_t sa = sbase + p * 24576u + tid * 32u;
            const __half* ga = Ab + (size_t)(t + 3) * 4096 + tid * 16;
            CP16(sa, ga); CP16(sa + 16, ga + 8);
            uint32_t sbB = sbase + p * 24576u + 8192u + tid * 64u;
            const __half* gb = Bb + (size_t)(t + 3) * 8192 + tid * 32;
            CP16(sbB, gb); CP16(sbB + 16, gb + 8); CP16(sbB + 32, gb + 16); CP16(sbB + 48, gb + 24);
        }
        CPCOMMITG();

        const uint32_t* as = smw + s * 6144;
        const uint32_t* bs = as + 2048;
#pragma unroll
        for (int ks = 0; ks < 2; ++ks) {
            uint4 af[4];
#pragma unroll
            for (int mi = 0; mi < 4; ++mi)
                af[mi] = *(const uint4*)(as + ((wr * 2 + ks) * 4 + mi) * 128 + lane * 4);
#pragma unroll
            for (int jp = 0; jp < 4; ++jp) {
                uint4 bf = *(const uint4*)(bs + ((ks * 4 + wc) * 4 + jp) * 128 + lane * 4);
#pragma unroll
                for (int mi = 0; mi < 4; ++mi) {
                    mma_h(acc[mi][jp * 2],     af[mi], bf.x, bf.y);
                    mma_h(acc[mi][jp * 2 + 1], af[mi], bf.z, bf.w);
                }
            }
        }
    }

    if (WB == 0) {
        float* C = (float*)Cv;
#pragma unroll
        for (int mi = 0; mi < 4; ++mi) {
            const int row0 = by * 128 + wr * 64 + mi * 16 + g;
#pragma unroll
            for (int j = 0; j < 8; ++j) {
                const int col = bx * 256 + wc * 64 + j * 8 + tg * 2;
                if (col < Nlim) {
                    float* p0 = C + (size_t)row0 * ldc + col;
                    float* p1 = p0 + 8 * ldc;
                    p0[0] = acc[mi][j][0]; p0[1] = acc[mi][j][1];
                    p1[0] = acc[mi][j][2]; p1[1] = acc[mi][j][3];
                }
            }
        }
    } else {
        // fused swiglu: odd wc warps hold gate cols of their 128-block
        __syncthreads();
        float* smf = (float*)smw;               // [blk(2)][c(64)][r stride 129]
        const int blk = wc >> 1;
        if (wc & 1) {
#pragma unroll
            for (int mi = 0; mi < 4; ++mi) {
                const int r = wr * 64 + mi * 16 + g;
#pragma unroll
                for (int j = 0; j < 8; ++j) {
                    const int c = j * 8 + tg * 2;
                    float* bp = smf + blk * 8256 + c * 129;
                    bp[r]           = silu_f(acc[mi][j][0]);
                    bp[129 + r]     = silu_f(acc[mi][j][1]);
                    bp[r + 8]       = silu_f(acc[mi][j][2]);
                    bp[129 + r + 8] = silu_f(acc[mi][j][3]);
                }
            }
        }
        __syncthreads();
        if (!(wc & 1)) {
            __half* cat = (__half*)Cv;
            const size_t mtb = (size_t)by * CAT_NKT * 4096;
#pragma unroll
            for (int mi = 0; mi < 4; ++mi) {
                const int r = wr * 64 + mi * 16 + g;
#pragma unroll
                for (int j = 0; j < 8; ++j) {
                    const int c = j * 8 + tg * 2;
                    const float* bp = smf + blk * 8256 + c * 129;
                    float t0 = acc[mi][j][0] * bp[r];
                    float t1 = acc[mi][j][1] * bp[129 + r];
                    float t2 = acc[mi][j][2] * bp[r + 8];
                    float t3 = acc[mi][j][3] * bp[129 + r + 8];
                    const int colg = bx * 128 + blk * 64 + c;
                    const int kt = colg >> 5, kk = colg & 31;
                    __half* tb = cat + mtb + (size_t)kt * 4096;
                    *(__half2*)(tb + ah_off(r, kk))     = __floats2half2_rn(t0, t1);
                    *(__half2*)(tb + ah_off(r + 8, kk)) = __floats2half2_rn(t2, t3);
                }
            }
        }
    }
}

// F1: ug GEMM (blocks 0..1023) + proj GEMM (blocks 1024..1151)
__global__ __launch_bounds__(256) void f1_kernel(
    const __half* __restrict__ xh, const __half* __restrict__ wp,
    const __half* __restrict__ wug, float* __restrict__ proj, __half* __restrict__ cat)
{
    extern __shared__ uint32_t smw[];
    const int bid = blockIdx.x;
    if (bid < 1024) gemm_body<1>(xh, wug, cat, 32, 0, 0, bid & 15, bid >> 4, smw);
    else { int b = bid - 1024; gemm_body<0>(xh, wp, proj, 32, PROJ_W, PROJ_W, b & 1, b >> 1, smw); }
}

__global__ __launch_bounds__(256) void gemm_cat_kernel(
    const __half* __restrict__ cat, const __half* __restrict__ wcat, float* __restrict__ out)
{
    extern __shared__ uint32_t smw[];
    gemm_body<0>(cat, wcat, out, CAT_NKT, H_DIM, H_DIM, blockIdx.x, blockIdx.y, smw);
}

// ---------------------------------------------------------------------------
// Single merged pack + decay kernel
// block ranges: [0,32768) xh | [32768,34816) wp | [34816,51200) wug |
//               [51200,59648) wcat | [59648,60672) decay
// ---------------------------------------------------------------------------
__global__ __launch_bounds__(256) void pack_all(
    const float* __restrict__ x,
    const float* __restrict__ Wk, const float* __restrict__ Wv,
    const float* __restrict__ Wql, const float* __restrict__ Wqr,
    const float* __restrict__ Wu, const float* __restrict__ Wg,
    const float* __restrict__ Wdn, const float* __restrict__ Wrc,
    const float* __restrict__ Wd,
    __half* __restrict__ xh, __half* __restrict__ wp, __half* __restrict__ wug,
    __half* __restrict__ wcat, float* __restrict__ dec)
{
    const int bid = blockIdx.x, tid = threadIdx.x;
    if (bid < 32768) {
        // x -> A tiles
        int o = bid * 256 + tid;
        int tile = o >> 12, hi = o & 4095;
        int mt = tile >> 5, kt = tile & 31;
        int wd = hi >> 1, e = hi & 1;
        int idx = wd >> 7, lane = (wd >> 2) & 31, q = wd & 3;
        int g = lane >> 2, tg = lane & 3, h = q & 1, u = q >> 1;
        int wr = idx >> 3, ks = (idx >> 2) & 1, mi = idx & 3;
        int m = wr * 64 + mi * 16 + h * 8 + g;
        int k = ks * 16 + u * 8 + tg * 2 + e;
        xh[o] = __float2half_rn(x[(size_t)(mt * 128 + m) * H_DIM + kt * 32 + k]);
    } else if (bid < 59648 + 0 && bid >= 59648) {
        // (placeholder to keep branch order readable; never taken)
    } else if (bid < 34816 || (bid >= 34816 && bid < 59648)) {
        int base, nkt, mode;
        if (bid < 34816)      { base = 32768; nkt = 32;      mode = 0; }
        else if (bid < 51200) { base = 34816; nkt = 32;      mode = 1; }
        else                  { base = 51200; nkt = CAT_NKT; mode = 2; }
        int o = (bid - base) * 256 + tid;
        int tile = o >> 13, hi = o & 8191;
        int nt = tile / nkt, ktile = tile - nt * nkt;
        int wd = hi >> 1, e = hi & 1;
        int idx = wd >> 7, lane = (wd >> 2) & 31, q = wd & 3;
        int g = lane >> 2, tg = lane & 3;
        int ks = idx >> 4, wc = (idx >> 2) & 3, jp = idx & 3;
        int j = jp * 2 + (q >> 1), r = q & 1;
        int nl = wc * 64 + j * 8 + g;
        int kg = ktile * 32 + ks * 16 + r * 8 + tg * 2 + e;
        int n = nt * 256 + nl;
        float v;
        if (mode == 0) {
            if (n < 128)      v = Wk[(size_t)kg * 128 + n];
            else if (n < 256) v = Wv[(size_t)kg * 128 + (n - 128)];
            else if (n < 320) v = Wql[(size_t)kg * 64 + (n - 256)];
            else if (n < 384) v = Wqr[(size_t)kg * 64 + (n - 320)];
            else              v = 0.0f;
            wp[o] = __float2half_rn(v);
        } else if (mode == 1) {
            int b = n >> 7, loc = n & 127;
            int col = b * 64 + (loc & 63);
            v = (loc < 64) ? Wu[(size_t)kg * LS_DIM + col] : Wg[(size_t)kg * LS_DIM + col];
            wug[o] = __float2half_rn(v);
        } else {
            v = (kg < 2048) ? Wdn[(size_t)kg * H_DIM + n] : Wrc[(size_t)(kg - 2048) * H_DIM + n];
            wcat[o] = __float2half_rn(v);
        }
    }
    if (bid >= 59648) {
        const int token = (bid - 59648) * 8 + (tid >> 5);
        const int lane = tid & 31;
        const float* xr = x + (size_t)token * H_DIM;
        float s = 0.0f;
#pragma unroll 8
        for (int jj = lane; jj < H_DIM; jj += 32) s = fmaf(xr[jj], Wd[jj], s);
#pragma unroll
        for (int o = 16; o; o >>= 1) s += __shfl_xor_sync(0xffffffffu, s, o);
        if (lane == 0) dec[token] = 1.0f / (1.0f + expf(-s));
    }
}

// ---------------------------------------------------------------------------
// Chunked scan (3 passes) — fp32
// ---------------------------------------------------------------------------
__global__ __launch_bounds__(512) void scan_pass1(
    const float* __restrict__ proj, const float* __restrict__ decay,
    float* __restrict__ cA, float* __restrict__ cB)
{
    const int b = blockIdx.y, c = blockIdx.x;
    const int tid = threadIdx.x;
    const int m = tid & 63, n0 = (tid >> 6) * 8;
    const size_t base = (size_t)b * SEQ + c * CHUNK;

    float st[8];
#pragma unroll
    for (int j = 0; j < 8; ++j) st[j] = 0.0f;
    float a = 1.0f;

    for (int s = 0; s < CHUNK; ++s) {
        const float* row = proj + (base + s) * PROJ_W;
        float d = decay[base + s];
        float k0 = row[m], k1 = row[64 + m];
        float4 v0a = *(const float4*)(row + 128 + n0);
        float4 v0b = *(const float4*)(row + 128 + n0 + 4);
        float4 v1a = *(const float4*)(row + 192 + n0);
        float4 v1b = *(const float4*)(row + 192 + n0 + 4);
        float v0[8] = {v0a.x, v0a.y, v0a.z, v0a.w, v0b.x, v0b.y, v0b.z, v0b.w};
        float v1[8] = {v1a.x, v1a.y, v1a.z, v1a.w, v1b.x, v1b.y, v1b.z, v1b.w};
        a *= d;
        float omd = 1.0f - d;
#pragma unroll
        for (int j = 0; j < 8; ++j) {
            float wv = 0.5f * (k0 * v0[j] + k1 * v1[j]);
            st[j] = fmaf(d, st[j], omd * wv);
        }
    }
    float* o = cB + ((size_t)(b * NCHUNK + c) * 64 + m) * 64 + n0;
#pragma unroll
    for (int j = 0; j < 8; ++j) o[j] = st[j];
    if (tid == 0) cA[b * NCHUNK + c] = a;
}

__global__ __launch_bounds__(512) void scan_pass2(
    const float* __restrict__ init_state, const float* __restrict__ cA,
    const float* __restrict__ cB, float* __restrict__ cS)
{
    const int b = blockIdx.x;
    const int i0 = threadIdx.x * 8;
    float st[8];
#pragma unroll
    for (int j = 0; j < 8; ++j) st[j] = init_state[i0 + j];
    for (int c = 0; c < NCHUNK; ++c) {
        const size_t o = (size_t)(b * NCHUNK + c) * 4096 + i0;
#pragma unroll
        for (int j = 0; j < 8; ++j) cS[o + j] = st[j];
        float a = cA[b * NCHUNK + c];
#pragma unroll
        for (int j = 0; j < 8; ++j) st[j] = fmaf(a, st[j], cB[o + j]);
    }
}

// 256 threads: nl = tid>>6 (0..3), grid (16, NCHUNK, BATCH)
__global__ __launch_bounds__(256) void scan_pass3(
    const float* __restrict__ proj, const float* __restrict__ decay,
    const float* __restrict__ cS, __half* __restrict__ cat)
{
    const int b = blockIdx.z, c = blockIdx.y;
    const int n0 = blockIdx.x * 4;
    const int tid = threadIdx.x;
    const int nl = tid >> 6;
    const int m = tid & 63;
    const int n = n0 + nl;
    const int lane = tid & 31;
    const int half_ = (m >> 5);

    __shared__ float part[2][4][2];

    float st = cS[(size_t)(b * NCHUNK + c) * 4096 + m * 64 + n];
    const size_t base = (size_t)b * SEQ + c * CHUNK;

    const float* row = proj + base * PROJ_W;
    float d = decay[base];
    float k0 = row[m], k1 = row[64 + m];
    float v0 = row[128 + n], v1 = row[192 + n];
    float qlm = row[256 + m], qrn = row[320 + n];

    for (int s = 0; s < CHUNK; ++s) {
        float nd = 0.f, nk0 = 0.f, nk1 = 0.f, nv0 = 0.f, nv1 = 0.f, nql = 0.f, nqr = 0.f;
        if (s + 1 < CHUNK) {
            const float* nr = proj + (base + s + 1) * PROJ_W;
            nd = decay[base + s + 1];
            nk0 = nr[m];       nk1 = nr[64 + m];
            nv0 = nr[128 + n]; nv1 = nr[192 + n];
            nql = nr[256 + m]; nqr = nr[320 + n];
        }
        float wv = 0.5f * (k0 * v0 + k1 * v1);
        st = fmaf(d, st, (1.0f - d) * wv);

        float p = qlm * st;
#pragma unroll
        for (int o = 16; o; o >>= 1) p += __shfl_xor_sync(0xffffffffu, p, o);
        if (lane == 0) part[s & 1][nl][half_] = p;
        __syncthreads();
        if (m == 0) {
            float rd = (part[s & 1][nl][0] + part[s & 1][nl][1]) * qrn;
            int token = (int)(base + s);
            int mt = token >> 7, r = token & 127;
            int kt = 64 + (n >> 5), kk = n & 31;
            cat[((size_t)mt * CAT_NKT + kt) * 4096 + ah_off(r, kk)] = __float2half_rn(silu_f(rd));
        }
        d = nd; k0 = nk0; k1 = nk1; v0 = nv0; v1 = nv1; qlm = nql; qrn = nqr;
    }
}

// ---------------------------------------------------------------------------
extern "C" void kernel_launch(void* const* d_in, const int* in_sizes, int n_in,
                              void* d_out, int out_size)
{
    const float* x       = (const float*)d_in[0];
    const float* W_decay = (const float*)d_in[1];
    const float* W_key   = (const float*)d_in[2];
    const float* W_value = (const float*)d_in[3];
    const float* W_ql    = (const float*)d_in[4];
    const float* W_qr    = (const float*)d_in[5];
    const float* W_rec   = (const float*)d_in[6];
    const float* W_up    = (const float*)d_in[7];
    const float* W_gate  = (const float*)d_in[8];
    const float* W_down  = (const float*)d_in[9];
    const float* init_st = (const float*)d_in[10];
    float* out = (float*)d_out;

    void *p_xh, *p_proj, *p_dec, *p_cat, *p_wp, *p_wug, *p_wcat, *p_cA, *p_cB, *p_cS;
    cudaGetSymbolAddress(&p_xh,   g_xh);
    cudaGetSymbolAddress(&p_proj, g_proj);
    cudaGetSymbolAddress(&p_dec,  g_decay);
    cudaGetSymbolAddress(&p_cat,  g_cat);
    cudaGetSymbolAddress(&p_wp,   g_wp);
    cudaGetSymbolAddress(&p_wug,  g_wug);
    cudaGetSymbolAddress(&p_wcat, g_wcat);
    cudaGetSymbolAddress(&p_cA,   g_cA);
    cudaGetSymbolAddress(&p_cB,   g_cB);
    cudaGetSymbolAddress(&p_cS,   g_cS);
    __half* xh   = (__half*)p_xh;
    float*  proj = (float*)p_proj;
    float*  dec  = (float*)p_dec;
    __half* cat  = (__half*)p_cat;
    __half* wp   = (__half*)p_wp;
    __half* wug  = (__half*)p_wug;
    __half* wcat = (__half*)p_wcat;
    float*  cA   = (float*)p_cA;
    float*  cB   = (float*)p_cB;
    float*  cS   = (float*)p_cS;

    cudaFuncSetAttribute(f1_kernel, cudaFuncAttributeMaxDynamicSharedMemorySize, 98304);
    cudaFuncSetAttribute(gemm_cat_kernel, cudaFuncAttributeMaxDynamicSharedMemorySize, 98304);

    // 1) all packs + decay in one launch
    pack_all<<<60672, 256>>>(x, W_key, W_value, W_ql, W_qr, W_up, W_gate,
                             W_down, W_rec, W_decay, xh, wp, wug, wcat, dec);

    // 2) ug GEMM (+fused swiglu -> cat kt 0..63)  ||  proj GEMM
    f1_kernel<<<1152, 256, 98304>>>(xh, wp, wug, proj, cat);

    // 3) chunked scan -> silu(reads) into cat kt 64..65
    scan_pass1<<<dim3(NCHUNK, BATCH), 512>>>(proj, dec, cA, cB);
    scan_pass2<<<BATCH, 512>>>(init_st, cA, cB, cS);
    scan_pass3<<<dim3(16, NCHUNK, BATCH), 256>>>(proj, dec, cS, cat);

    // 4) out = [t|sr] @ [W_down;W_rec]
    gemm_cat_kernel<<<dim3(4, 64), 256, 98304>>>(cat, wcat, out);
}

// round 8
// speedup vs baseline: 1.2448x; 1.2448x over previous
#include <cuda_runtime.h>
#include <cuda_fp16.h>
#include <math.h>
#include <stdint.h>

#define H_DIM   1024
#define M_DIM   64
#define LS_DIM  2048
#define BATCH   4
#define SEQ     2048
#define NTOK    8192
#define PROJ_W  384
#define CHUNK   64
#define NCHUNK  32
#define CAT_NKT 66            // 64 ktiles of t (k=2048) + 2 ktiles of sr (k=64)

// -------- scratch (device globals; allocation-free rule) --------------------
__device__ __half g_xh[(size_t)NTOK * H_DIM];               // x, A-frag tiles [mt][kt][4096h]
__device__ float  g_proj[(size_t)NTOK * PROJ_W];            // natural row-major fp32
__device__ float  g_decay[NTOK];
__device__ __half g_cat[(size_t)64 * CAT_NKT * 4096];       // [t|sr] A-frag tiles
__device__ __half g_wp[(size_t)3 * 32 * 4096];              // B-frag tiles: [Wk|Wv|Wql|Wqr]
__device__ __half g_wug[(size_t)32 * 32 * 4096];            // B-frag tiles: [u64|g64] x32
__device__ __half g_wcat[(size_t)8 * CAT_NKT * 4096];       // B-frag tiles: [Wdown;Wrec]
__device__ float  g_cA[BATCH * NCHUNK];
__device__ float  g_cB[(size_t)BATCH * NCHUNK * 4096];
__device__ float  g_cS[(size_t)BATCH * NCHUNK * 4096];

// ---------------------------------------------------------------------------
__device__ __forceinline__ float silu_f(float x) { return x / (1.0f + expf(-x)); }

__device__ __forceinline__ void mma_h(float* c, uint4 a, uint32_t b0, uint32_t b1) {
    asm volatile(
        "mma.sync.aligned.m16n8k16.row.col.f32.f16.f16.f32 "
        "{%0,%1,%2,%3}, {%4,%5,%6,%7}, {%8,%9}, {%0,%1,%2,%3};"
        : "+f"(c[0]), "+f"(c[1]), "+f"(c[2]), "+f"(c[3])
        : "r"(a.x), "r"(a.y), "r"(a.z), "r"(a.w), "r"(b0), "r"(b1));
}

#define CP16(s, g)  asm volatile("cp.async.cg.shared.global [%0], [%1], 16;" :: "r"(s), "l"(g))
#define CPCOMMITG() asm volatile("cp.async.commit_group;" ::: "memory")
#define CPWAIT1()   asm volatile("cp.async.wait_group 1;" ::: "memory")

// A-frag-major half offset within a 128(m) x 32(k) tile (4096 halfs).
__device__ __forceinline__ int ah_off(int m, int k) {
    int wr = m >> 5, mi = (m >> 4) & 1, h = (m >> 3) & 1, g = m & 7;
    int ks = k >> 4, u = (k >> 3) & 1, tg = (k >> 1) & 3, e = k & 1;
    int word = ((wr * 4 + ks * 2 + mi) * 32 + g * 4 + tg) * 4 + h + 2 * u;
    return word * 2 + e;
}

// ---------------------------------------------------------------------------
// fp16 tensor-core GEMM. 256 threads = 8 warps (4x2), warp tile 32x64.
// BM=BN=128, ktile = 32. Frag-major operands, cp.async 3-stage pipeline.
// WB 0: natural fp32 store to C (ldc). WB 1: fused swiglu -> g_cat half tiles.
// ---------------------------------------------------------------------------
template <int WB>
__global__ __launch_bounds__(256, 2) void gemm_h(
    const __half* __restrict__ A, const __half* __restrict__ B, void* __restrict__ Cv,
    int nkt, int ldc)
{
    __shared__ uint32_t sm[12288];           // 3 stages x (2048 A + 2048 B) words

    const int tid = threadIdx.x;
    const int w = tid >> 5, lane = tid & 31;
    const int wr = w & 3, wc = w >> 2;
    const int g = lane >> 2, tg = lane & 3;

    const __half* Abase = A + (size_t)blockIdx.y * nkt * 4096 + tid * 16;
    const __half* Bbase = B + (size_t)blockIdx.x * nkt * 4096 + tid * 16;
    const uint32_t sb = (uint32_t)__cvta_generic_to_shared(sm);

    float acc[2][8][4];
#pragma unroll
    for (int mi = 0; mi < 2; ++mi)
#pragma unroll
        for (int j = 0; j < 8; ++j)
#pragma unroll
            for (int q = 0; q < 4; ++q) acc[mi][j][q] = 0.0f;

    // prologue: stages 0,1
#pragma unroll
    for (int p = 0; p < 2; ++p) {
        uint32_t sa = sb + p * 16384u + tid * 32u;
        const __half* ga = Abase + (size_t)p * 4096;
        const __half* gb = Bbase + (size_t)p * 4096;
        CP16(sa, ga); CP16(sa + 16, ga + 8);
        CP16(sa + 8192, gb); CP16(sa + 8208, gb + 8);
        CPCOMMITG();
    }

    for (int t = 0; t < nkt; ++t) {
        const int s = t - (t / 3) * 3;
        CPWAIT1();
        __syncthreads();
        if (t + 2 < nkt) {
            const int s2 = (t + 2) - ((t + 2) / 3) * 3;
            uint32_t sa = sb + s2 * 16384u + tid * 32u;
            const __half* ga = Abase + (size_t)(t + 2) * 4096;
            const __half* gb = Bbase + (size_t)(t + 2) * 4096;
            CP16(sa, ga); CP16(sa + 16, ga + 8);
            CP16(sa + 8192, gb); CP16(sa + 8208, gb + 8);
        }
        CPCOMMITG();

        const uint32_t* as = sm + s * 4096;
        const uint32_t* bs = as + 2048;
#pragma unroll
        for (int ks = 0; ks < 2; ++ks) {
            uint4 af0 = *(const uint4*)(as + (wr * 4 + ks * 2 + 0) * 128 + lane * 4);
            uint4 af1 = *(const uint4*)(as + (wr * 4 + ks * 2 + 1) * 128 + lane * 4);
#pragma unroll
            for (int jp = 0; jp < 4; ++jp) {
                uint4 bf = *(const uint4*)(bs + ((ks * 2 + wc) * 4 + jp) * 128 + lane * 4);
                mma_h(acc[0][jp * 2],     af0, bf.x, bf.y);
                mma_h(acc[1][jp * 2],     af1, bf.x, bf.y);
                mma_h(acc[0][jp * 2 + 1], af0, bf.z, bf.w);
                mma_h(acc[1][jp * 2 + 1], af1, bf.z, bf.w);
            }
        }
    }

    if (WB == 0) {
        float* C = (float*)Cv;
#pragma unroll
        for (int mi = 0; mi < 2; ++mi) {
            const int row0 = blockIdx.y * 128 + wr * 32 + mi * 16 + g;
#pragma unroll
            for (int j = 0; j < 8; ++j) {
                const int col = blockIdx.x * 128 + wc * 64 + j * 8 + tg * 2;
                float* p0 = C + (size_t)row0 * ldc + col;
                float* p1 = p0 + 8 * ldc;
                p0[0] = acc[mi][j][0]; p0[1] = acc[mi][j][1];
                p1[0] = acc[mi][j][2]; p1[1] = acc[mi][j][3];
            }
        }
    } else {
        // fused swiglu: wc==1 warps hold gate; exchange silu(gate) via smem
        __syncthreads();
        float* smf = (float*)sm;               // [c][r], stride 129
        if (wc == 1) {
#pragma unroll
            for (int mi = 0; mi < 2; ++mi) {
                const int r = wr * 32 + mi * 16 + g;
#pragma unroll
                for (int j = 0; j < 8; ++j) {
                    const int c = j * 8 + tg * 2;
                    smf[c * 129 + r]           = silu_f(acc[mi][j][0]);
                    smf[(c + 1) * 129 + r]     = silu_f(acc[mi][j][1]);
                    smf[c * 129 + r + 8]       = silu_f(acc[mi][j][2]);
                    smf[(c + 1) * 129 + r + 8] = silu_f(acc[mi][j][3]);
                }
            }
        }
        __syncthreads();
        if (wc == 0) {
            __half* Ch = (__half*)Cv;
            const size_t mtb = (size_t)blockIdx.y * CAT_NKT * 4096;
#pragma unroll
            for (int mi = 0; mi < 2; ++mi) {
                const int r = wr * 32 + mi * 16 + g;
#pragma unroll
                for (int j = 0; j < 8; ++j) {
                    const int c = j * 8 + tg * 2;
                    float t0 = acc[mi][j][0] * smf[c * 129 + r];
                    float t1 = acc[mi][j][1] * smf[(c + 1) * 129 + r];
                    float t2 = acc[mi][j][2] * smf[c * 129 + r + 8];
                    float t3 = acc[mi][j][3] * smf[(c + 1) * 129 + r + 8];
                    const int colg = blockIdx.x * 64 + c;
                    const int kt = colg >> 5, kk = colg & 31;
                    __half* tb = Ch + mtb + (size_t)kt * 4096;
                    *(__half2*)(tb + ah_off(r, kk))     = __floats2half2_rn(t0, t1);
                    *(__half2*)(tb + ah_off(r + 8, kk)) = __floats2half2_rn(t2, t3);
                }
            }
        }
    }
}

// ---------------------------------------------------------------------------
// Packers (gather by output half index)
// ---------------------------------------------------------------------------
__global__ __launch_bounds__(256) void pack_xh(const float* __restrict__ x, __half* __restrict__ out)
{
    int o = blockIdx.x * 256 + threadIdx.x;       // NTOK * H halfs
    int tile = o >> 12, hi = o & 4095;
    int wd = hi >> 1, e = hi & 1;
    int idx = wd >> 7, lane = (wd >> 2) & 31, reg = wd & 3;
    int g = lane >> 2, tg = lane & 3;
    int wr = idx >> 2, ks = (idx >> 1) & 1, mi = idx & 1, h = reg & 1, u = reg >> 1;
    int m = wr * 32 + mi * 16 + h * 8 + g;
    int k = ks * 16 + u * 8 + tg * 2 + e;
    int mt = tile >> 5, kt = tile & 31;
    out[o] = __float2half_rn(x[(size_t)(mt * 128 + m) * H_DIM + kt * 32 + k]);
}

// B-frag packer. mode 0: wp (nkt=32), 1: wug (nkt=32), 2: wcat (nkt=66)
__global__ __launch_bounds__(256) void pack_bh(
    const float* __restrict__ S0, const float* __restrict__ S1,
    const float* __restrict__ S2, const float* __restrict__ S3,
    __half* __restrict__ out, int mode, int nkt)
{
    int o = blockIdx.x * 256 + threadIdx.x;
    int tile = o >> 12, hi = o & 4095;
    int nt = tile / nkt, kt = tile - nt * nkt;
    int wd = hi >> 1, e = hi & 1;
    int idx = wd >> 7, lane = (wd >> 2) & 31, wreg = wd & 3;
    int g = lane >> 2, tg = lane & 3;
    int jp = idx & 3, t2 = idx >> 2;
    int ks = t2 >> 1, wc = t2 & 1;
    int j = jp * 2 + (wreg >> 1), r = wreg & 1;
    int nl = wc * 64 + j * 8 + g;
    int kg = kt * 32 + ks * 16 + r * 8 + tg * 2 + e;

    float v;
    if (mode == 0) {
        int n = nt * 128 + nl;
        if (n < 128)      v = S0[(size_t)kg * 128 + n];
        else if (n < 256) v = S1[(size_t)kg * 128 + (n - 128)];
        else if (n < 320) v = S2[(size_t)kg * 64 + (n - 256)];
        else              v = S3[(size_t)kg * 64 + (n - 320)];
    } else if (mode == 1) {
        int col = nt * 64 + (nl & 63);
        v = (nl < 64) ? S0[(size_t)kg * LS_DIM + col] : S1[(size_t)kg * LS_DIM + col];
    } else {
        int n = nt * 128 + nl;
        v = (kg < 2048) ? S0[(size_t)kg * H_DIM + n] : S1[(size_t)(kg - 2048) * H_DIM + n];
    }
    out[o] = __float2half_rn(v);
}

// ---------------------------------------------------------------------------
__global__ __launch_bounds__(256) void decay_kernel(
    const float* __restrict__ x, const float* __restrict__ Wd, float* __restrict__ dec)
{
    const int token = blockIdx.x * 8 + (threadIdx.x >> 5);
    const int lane = threadIdx.x & 31;
    const float* xr = x + (size_t)token * H_DIM;
    float s = 0.0f;
#pragma unroll 8
    for (int j = lane; j < H_DIM; j += 32) s = fmaf(xr[j], Wd[j], s);
#pragma unroll
    for (int o = 16; o; o >>= 1) s += __shfl_xor_sync(0xffffffffu, s, o);
    if (lane == 0) dec[token] = 1.0f / (1.0f + expf(-s));
}

// ---------------------------------------------------------------------------
// Chunked scan — fp32
// pass1: per-chunk local accumulation (A_c, B_c)
// pass2 (PARALLEL): cS[b,c] = (prod_{j<c} a_j)*init + sum_{j<c} (prod_{j<i<c} a_i)*B_j
//   computed per (c,b) block with a backward running product — no serial chain.
// pass3: recompute within chunk from cS and emit silu(reads).
// ---------------------------------------------------------------------------
__global__ __launch_bounds__(512) void scan_pass1(
    const float* __restrict__ proj, const float* __restrict__ decay,
    float* __restrict__ cA, float* __restrict__ cB)
{
    const int b = blockIdx.y, c = blockIdx.x;
    const int tid = threadIdx.x;
    const int m = tid & 63, n0 = (tid >> 6) * 8;
    const size_t base = (size_t)b * SEQ + c * CHUNK;

    float st[8];
#pragma unroll
    for (int j = 0; j < 8; ++j) st[j] = 0.0f;
    float a = 1.0f;

    for (int s = 0; s < CHUNK; ++s) {
        const float* row = proj + (base + s) * PROJ_W;
        float d = decay[base + s];
        float k0 = row[m], k1 = row[64 + m];
        float4 v0a = *(const float4*)(row + 128 + n0);
        float4 v0b = *(const float4*)(row + 128 + n0 + 4);
        float4 v1a = *(const float4*)(row + 192 + n0);
        float4 v1b = *(const float4*)(row + 192 + n0 + 4);
        float v0[8] = {v0a.x, v0a.y, v0a.z, v0a.w, v0b.x, v0b.y, v0b.z, v0b.w};
        float v1[8] = {v1a.x, v1a.y, v1a.z, v1a.w, v1b.x, v1b.y, v1b.z, v1b.w};
        a *= d;
        float omd = 1.0f - d;
#pragma unroll
        for (int j = 0; j < 8; ++j) {
            float wv = 0.5f * (k0 * v0[j] + k1 * v1[j]);
            st[j] = fmaf(d, st[j], omd * wv);
        }
    }
    float* o = cB + ((size_t)(b * NCHUNK + c) * 64 + m) * 64 + n0;
#pragma unroll
    for (int j = 0; j < 8; ++j) o[j] = st[j];
    if (tid == 0) cA[b * NCHUNK + c] = a;
}

// grid (NCHUNK, BATCH), 512 threads, 8 elems/thread
__global__ __launch_bounds__(512) void scan_pass2(
    const float* __restrict__ init_state, const float* __restrict__ cA,
    const float* __restrict__ cB, float* __restrict__ cS)
{
    const int c = blockIdx.x, b = blockIdx.y;
    const int i0 = threadIdx.x * 8;
    __shared__ float sa[NCHUNK];
    if ((int)threadIdx.x < c) sa[threadIdx.x] = cA[b * NCHUNK + threadIdx.x];
    __syncthreads();

    float st[8];
#pragma unroll
    for (int j = 0; j < 8; ++j) st[j] = 0.0f;
    float w = 1.0f;

    for (int j = c - 1; j >= 0; --j) {
        const float* Bp = cB + (size_t)(b * NCHUNK + j) * 4096 + i0;
        float4 b0 = *(const float4*)Bp;
        float4 b1 = *(const float4*)(Bp + 4);
        st[0] = fmaf(w, b0.x, st[0]); st[1] = fmaf(w, b0.y, st[1]);
        st[2] = fmaf(w, b0.z, st[2]); st[3] = fmaf(w, b0.w, st[3]);
        st[4] = fmaf(w, b1.x, st[4]); st[5] = fmaf(w, b1.y, st[5]);
        st[6] = fmaf(w, b1.z, st[6]); st[7] = fmaf(w, b1.w, st[7]);
        w *= sa[j];
    }
    // + (prod_{j<c} a_j) * init_state
    const float* ip = init_state + i0;
    float* o = cS + (size_t)(b * NCHUNK + c) * 4096 + i0;
#pragma unroll
    for (int j = 0; j < 8; ++j) o[j] = fmaf(w, ip[j], st[j]);
}

__global__ __launch_bounds__(512) void scan_pass3(
    const float* __restrict__ proj, const float* __restrict__ decay,
    const float* __restrict__ cS, __half* __restrict__ cat)
{
    const int b = blockIdx.z, c = blockIdx.y;
    const int n0 = blockIdx.x * 8;
    const int tid = threadIdx.x;
    const int nl = tid >> 6;
    const int m = tid & 63;
    const int n = n0 + nl;
    const int lane = tid & 31;
    const int half_ = (m >> 5);

    __shared__ float part[2][8][2];

    float st = cS[(size_t)(b * NCHUNK + c) * 4096 + m * 64 + n];
    const size_t base = (size_t)b * SEQ + c * CHUNK;

    const float* row = proj + base * PROJ_W;
    float d = decay[base];
    float k0 = row[m], k1 = row[64 + m];
    float v0 = row[128 + n], v1 = row[192 + n];
    float qlm = row[256 + m], qrn = row[320 + n];

    for (int s = 0; s < CHUNK; ++s) {
        float nd = 0.f, nk0 = 0.f, nk1 = 0.f, nv0 = 0.f, nv1 = 0.f, nql = 0.f, nqr = 0.f;
        if (s + 1 < CHUNK) {
            const float* nr = proj + (base + s + 1) * PROJ_W;
            nd = decay[base + s + 1];
            nk0 = nr[m];       nk1 = nr[64 + m];
            nv0 = nr[128 + n]; nv1 = nr[192 + n];
            nql = nr[256 + m]; nqr = nr[320 + n];
        }
        float wv = 0.5f * (k0 * v0 + k1 * v1);
        st = fmaf(d, st, (1.0f - d) * wv);

        float p = qlm * st;
#pragma unroll
        for (int o = 16; o; o >>= 1) p += __shfl_xor_sync(0xffffffffu, p, o);
        if (lane == 0) part[s & 1][nl][half_] = p;
        __syncthreads();
        if (m == 0) {
            float rd = (part[s & 1][nl][0] + part[s & 1][nl][1]) * qrn;
            int token = (int)(base + s);
            int mt = token >> 7, r = token & 127;
            int kt = 64 + (n >> 5), kk = n & 31;
            cat[((size_t)mt * CAT_NKT + kt) * 4096 + ah_off(r, kk)] = __float2half_rn(silu_f(rd));
        }
        d = nd; k0 = nk0; k1 = nk1; v0 = nv0; v1 = nv1; qlm = nql; qrn = nqr;
    }
}

// ---------------------------------------------------------------------------
extern "C" void kernel_launch(void* const* d_in, const int* in_sizes, int n_in,
                              void* d_out, int out_size)
{
    const float* x       = (const float*)d_in[0];
    const float* W_decay = (const float*)d_in[1];
    const float* W_key   = (const float*)d_in[2];
    const float* W_value = (const float*)d_in[3];
    const float* W_ql    = (const float*)d_in[4];
    const float* W_qr    = (const float*)d_in[5];
    const float* W_rec   = (const float*)d_in[6];
    const float* W_up    = (const float*)d_in[7];
    const float* W_gate  = (const float*)d_in[8];
    const float* W_down  = (const float*)d_in[9];
    const float* init_st = (const float*)d_in[10];
    float* out = (float*)d_out;

    void *p_xh, *p_proj, *p_dec, *p_cat, *p_wp, *p_wug, *p_wcat, *p_cA, *p_cB, *p_cS;
    cudaGetSymbolAddress(&p_xh,   g_xh);
    cudaGetSymbolAddress(&p_proj, g_proj);
    cudaGetSymbolAddress(&p_dec,  g_decay);
    cudaGetSymbolAddress(&p_cat,  g_cat);
    cudaGetSymbolAddress(&p_wp,   g_wp);
    cudaGetSymbolAddress(&p_wug,  g_wug);
    cudaGetSymbolAddress(&p_wcat, g_wcat);
    cudaGetSymbolAddress(&p_cA,   g_cA);
    cudaGetSymbolAddress(&p_cB,   g_cB);
    cudaGetSymbolAddress(&p_cS,   g_cS);
    __half* xh   = (__half*)p_xh;
    float*  proj = (float*)p_proj;
    float*  dec  = (float*)p_dec;
    __half* cat  = (__half*)p_cat;
    __half* wp   = (__half*)p_wp;
    __half* wug  = (__half*)p_wug;
    __half* wcat = (__half*)p_wcat;
    float*  cA   = (float*)p_cA;
    float*  cB   = (float*)p_cB;
    float*  cS   = (float*)p_cS;

    const dim3 b256(256), b512(512);

    // packs
    pack_xh<<<(NTOK * H_DIM) / 256, b256>>>(x, xh);
    pack_bh<<<(3 * 32 * 4096) / 256, b256>>>(W_key, W_value, W_ql, W_qr, wp, 0, 32);
    pack_bh<<<(32 * 32 * 4096) / 256, b256>>>(W_up, W_gate, nullptr, nullptr, wug, 1, 32);
    pack_bh<<<(8 * CAT_NKT * 4096) / 256, b256>>>(W_down, W_rec, nullptr, nullptr, wcat, 2, CAT_NKT);
    decay_kernel<<<NTOK / 8, b256>>>(x, W_decay, dec);

    // projections: N=384 natural fp32 -> g_proj
    gemm_h<0><<<dim3(3, 64), b256>>>(xh, wp, proj, 32, PROJ_W);

    // chunked scan -> silu(reads) into cat ktiles 64..65
    scan_pass1<<<dim3(NCHUNK, BATCH), b512>>>(proj, dec, cA, cB);
    scan_pass2<<<dim3(NCHUNK, BATCH), b512>>>(init_st, cA, cB, cS);
    scan_pass3<<<dim3(8, NCHUNK, BATCH), b512>>>(proj, dec, cS, cat);

    // FFN up|gate + fused swiglu -> cat ktiles 0..63
    gemm_h<1><<<dim3(32, 64), b256>>>(xh, wug, cat, 32, 0);

    // out = [t|sr] @ [W_down;W_rec]  (single GEMM, K=2112)
    gemm_h<0><<<dim3(8, 64), b256>>>(cat, wcat, out, CAT_NKT, H_DIM);
}